// round 15
// baseline (speedup 1.0000x reference)
#include <cuda_runtime.h>
#include <cstdint>
#include <math.h>

// Shapes (fixed by the problem)
#define NSENT 4096
#define L     512
#define LQ    32
#define D     30
#define AF    10
#define KK    4

#define TPB 480          // 480*4 % 30 == 0 -> fixed channel phase per thread
#define GRP 16           // sentences per tail group
#define NGRP (NSENT / GRP)
#define PITCH 31         // table row pitch (avoid bank conflicts)

__device__ float        g_S[NSENT][D];
__device__ float4       g_Z[NSENT][D];
__device__ float        g_costs[NSENT];
__device__ unsigned int g_grp[NGRP];   // mod-16 epoch counters (never reset)
__device__ unsigned int g_fin;         // mod-NGRP epoch counter

// Boundary z-vector: bc[o] = sum_j dot(w1[o][j][0..3], z[j])
//   z = ( x3+2x4+3x5,  x0+x4+2x5,  2x0+x1+x5,  3x0+2x1+x2 )
__device__ __forceinline__ float4 make_z(float x0, float x1, float x2,
                                         float x3, float x4, float x5)
{
    return make_float4(x3 + 2.f * x4 + 3.f * x5,
                       x0 + x4 + 2.f * x5,
                       2.f * x0 + x1 + x5,
                       3.f * x0 + 2.f * x1 + x2);
}

__global__ __launch_bounds__(TPB, 3) void fused_kernel(
    const float* __restrict__ se, const float* __restrict__ qe,
    const float* __restrict__ gaf, const int* __restrict__ labels,
    const float* __restrict__ w1, const float* __restrict__ b1,
    const float* __restrict__ w2, const float* __restrict__ b2,
    const float* __restrict__ lw, const float* __restrict__ lb,
    float* __restrict__ out)
{
    __shared__ float4 part4[TPB];
    __shared__ float4 sWv[D * PITCH];
    __shared__ float  sW2s[D * PITCH];
    __shared__ float  q0[32], q1g[32], q2g[32], qT[32], qn[3];
    __shared__ float4 qzv[32];
    __shared__ float  sS[GRP][32], sT[GRP][32];
    __shared__ float4 zbuf[GRP][32];
    __shared__ int    sh_do, sh_last;

    const int n = blockIdx.x;
    const int tid = threadIdx.x;
    const int w = tid / 32, o = tid % 32;

    // ---- Phase 1: pure streaming column-sum (measured ~7.6 TB/s; unchanged) ----
    {
        const float4* p = reinterpret_cast<const float4*>(se) + (size_t)n * (L * D / 4);

        float4 v0 = __ldcs(p + tid + TPB * 0);
        float4 v1 = __ldcs(p + tid + TPB * 1);
        float4 v2 = __ldcs(p + tid + TPB * 2);
        float4 v3 = __ldcs(p + tid + TPB * 3);
        float ax = (v0.x + v1.x) + (v2.x + v3.x);
        float ay = (v0.y + v1.y) + (v2.y + v3.y);
        float az = (v0.z + v1.z) + (v2.z + v3.z);
        float aw = (v0.w + v1.w) + (v2.w + v3.w);

        float4 u0 = __ldcs(p + tid + TPB * 4);
        float4 u1 = __ldcs(p + tid + TPB * 5);
        float4 u2 = __ldcs(p + tid + TPB * 6);
        float4 u3 = __ldcs(p + tid + TPB * 7);
        ax += (u0.x + u1.x) + (u2.x + u3.x);
        ay += (u0.y + u1.y) + (u2.y + u3.y);
        az += (u0.z + u1.z) + (u2.z + u3.z);
        aw += (u0.w + u1.w) + (u2.w + u3.w);

        part4[tid] = make_float4(ax, ay, az, aw);
    }
    __syncthreads();

    if (tid < D) {
        const float* part = reinterpret_cast<const float*>(part4);
        float s = 0.f;
        #pragma unroll
        for (int k = 0; k < (TPB * 4) / D; k++)
            s += part[tid + D * k];
        g_S[n][tid] = s;

        const float* base = se + (size_t)n * (L * D);
        float x0 = base[0 * D + tid];
        float x1 = base[1 * D + tid];
        float x2 = base[2 * D + tid];
        float x3 = base[(L - 3) * D + tid];
        float x4 = base[(L - 2) * D + tid];
        float x5 = base[(L - 1) * D + tid];
        g_Z[n][tid] = make_z(x0, x1, x2, x3, x4, x5);
    }
    __syncthreads();

    // ---- Group-completion handoff: 15/16 CTAs exit here ----
    if (tid == 0) {
        __threadfence();
        unsigned int old = atomicAdd(&g_grp[n >> 4], 1u);
        sh_do = ((old & (GRP - 1u)) == GRP - 1u) ? 1 : 0;
    }
    __syncthreads();
    if (!sh_do) return;
    __threadfence();   // make peers' g_S/g_Z writes visible

    // ---- Phase 2 (1 CTA per 16 sentences): tail math, overlapped chip-wide ----
    const int gbase = (n >> 4) << 4;

    for (int i = tid; i < D * D; i += TPB) {
        int oo = i / D, jj = i % D;
        sWv[oo * PITCH + jj] = *reinterpret_cast<const float4*>(w1 + i * KK);
        const float* vv = w2 + i * KK;
        sW2s[oo * PITCH + jj] = vv[0] + vv[1] + vv[2] + vv[3];
    }
    if (w == 0) {
        float Sq = 0.f;
        if (o < D) {
            #pragma unroll
            for (int t = 0; t < LQ; t++) Sq += qe[t * D + o];
            float x0 = qe[0 * D + o],        x1 = qe[1 * D + o],        x2 = qe[2 * D + o];
            float x3 = qe[(LQ - 3) * D + o], x4 = qe[(LQ - 2) * D + o], x5 = qe[(LQ - 1) * D + o];
            qzv[o] = make_z(x0, x1, x2, x3, x4, x5);
        }
        q0[o] = (o < D) ? Sq : 0.f;
    }
    __syncthreads();   // tables + question inputs staged

    // Warp 0: question side
    if (w == 0) {
        const float invLq3 = 1.f / (float)(LQ + 3);
        float q1 = 0.f, Tv = 0.f;
        if (o < D) {
            float ds = 0.f, bc = 0.f;
            #pragma unroll
            for (int j = 0; j < D; j++) {
                float4 wv = sWv[o * PITCH + j];
                float ws = (wv.x + wv.y) + (wv.z + wv.w);
                ds += ws * q0[j];
                float4 z = qzv[j];
                bc += wv.x * z.x + wv.y * z.y + wv.z * z.z + wv.w * z.w;
            }
            q1 = b1[o] + ds * invLq3;
            Tv = (float)LQ * b1[o] + ds - 0.25f * bc;
        }
        q1g[o] = q1;
        qT[o] = Tv;
        __syncwarp();

        float q2 = 0.f;
        if (o < D) {
            float d2 = 0.f;
            #pragma unroll
            for (int j = 0; j < D; j++) d2 += sW2s[o * PITCH + j] * qT[j];
            q2 = b2[o] + d2 * invLq3;
        }
        q2g[o] = q2;
        __syncwarp();

        float n0 = q0[o] * q0[o];
        float n1 = q1 * q1;
        float n2 = q2 * q2;
        #pragma unroll
        for (int off = 16; off; off >>= 1) {
            n0 += __shfl_down_sync(0xffffffffu, n0, off);
            n1 += __shfl_down_sync(0xffffffffu, n1, off);
            n2 += __shfl_down_sync(0xffffffffu, n2, off);
        }
        if (o == 0) {
            qn[0] = rsqrtf(n0);
            qn[1] = rsqrtf(n1);
            qn[2] = rsqrtf(n2);
        }
    }

    // 16 sentences across 15 warps (warp 0 also takes sidx 15)
    float Svv[2], s1v[2], s2v[2];
    const float inv515 = 1.f / (float)(L + 3);
    #pragma unroll
    for (int rep = 0; rep < 2; rep++) {
        int sidx = w + rep * 15;
        Svv[rep] = 0.f; s1v[rep] = 0.f; s2v[rep] = 0.f;
        if (sidx < GRP) {
            int n2 = gbase + sidx;
            float Sv = 0.f;
            if (o < D) {
                Sv = g_S[n2][o];
                zbuf[sidx][o] = g_Z[n2][o];
            }
            sS[sidx][o] = Sv;
            Svv[rep] = Sv;
            __syncwarp();

            float s1 = 0.f, Tv = 0.f;
            if (o < D) {
                float ds = 0.f, bc = 0.f;
                #pragma unroll
                for (int j = 0; j < D; j++) {
                    float4 wv = sWv[o * PITCH + j];
                    float ws = (wv.x + wv.y) + (wv.z + wv.w);
                    ds += ws * sS[sidx][j];
                    float4 z = zbuf[sidx][j];
                    bc += wv.x * z.x + wv.y * z.y + wv.z * z.z + wv.w * z.w;
                }
                s1 = b1[o] + ds * inv515;
                Tv = (float)L * b1[o] + ds - 0.25f * bc;
            }
            sT[sidx][o] = Tv;
            __syncwarp();

            float s2 = 0.f;
            if (o < D) {
                float d2 = 0.f;
                #pragma unroll
                for (int j = 0; j < D; j++) d2 += sW2s[o * PITCH + j] * sT[sidx][j];
                s2 = b2[o] + d2 * inv515;
            }
            s1v[rep] = s1;
            s2v[rep] = s2;
        }
    }
    __syncthreads();   // question-side results visible

    #pragma unroll
    for (int rep = 0; rep < 2; rep++) {
        int sidx = w + rep * 15;
        if (sidx < GRP) {
            int n2 = gbase + sidx;
            float Sv = Svv[rep], s1 = s1v[rep], s2 = s2v[rep];
            float qr = 0.f, q1v = 0.f, q2v = 0.f;
            if (o < D) { qr = q0[o]; q1v = q1g[o]; q2v = q2g[o]; }

            float p0 = Sv * qr, p1 = Sv * q2v, p2 = Sv * Sv;
            float p3 = s1 * q1v, p4 = s1 * s1, p5 = s2 * q2v, p6 = s2 * s2;
            #pragma unroll
            for (int off = 16; off; off >>= 1) {
                p0 += __shfl_down_sync(0xffffffffu, p0, off);
                p1 += __shfl_down_sync(0xffffffffu, p1, off);
                p2 += __shfl_down_sync(0xffffffffu, p2, off);
                p3 += __shfl_down_sync(0xffffffffu, p3, off);
                p4 += __shfl_down_sync(0xffffffffu, p4, off);
                p5 += __shfl_down_sync(0xffffffffu, p5, off);
                p6 += __shfl_down_sync(0xffffffffu, p6, off);
            }
            if (o == 0) {
                float inv_nS = rsqrtf(p2);
                float sim1 = (n2 == 0) ? (p0 * qn[0] * inv_nS)
                                       : (p1 * qn[2] * inv_nS);
                float sim2 = p3 * rsqrtf(p4) * qn[1];
                float sim3 = p5 * rsqrtf(p6) * qn[2];

                const float* g = gaf + (size_t)n2 * AF;
                float l0 = lb[0] + lw[0] * sim1 + lw[1] * sim2 + lw[2] * sim3;
                float l1 = lb[1] + lw[13] * sim1 + lw[14] * sim2 + lw[15] * sim3;
                #pragma unroll
                for (int f = 0; f < AF; f++) {
                    float gv = g[f];
                    l0 += lw[3 + f] * gv;
                    l1 += lw[16 + f] * gv;
                }
                float mx = fmaxf(l0, l1);
                float lse = mx + logf(expf(l0 - mx) + expf(l1 - mx));
                float lp0 = l0 - lse, lp1 = l1 - lse;
                float e0 = expf(lp0), e1 = expf(lp1);
                out[1 + n2] = e1 / (e0 + e1);
                int lab = labels[n2];
                g_costs[n2] = -(lab ? lp1 : lp0);
            }
        }
    }

    // ---- Final: last tail CTA does the deterministic cost reduction ----
    __syncthreads();
    if (tid == 0) {
        __threadfence();
        unsigned int old = atomicAdd(&g_fin, 1u);
        sh_last = ((old % NGRP) == NGRP - 1u) ? 1 : 0;
    }
    __syncthreads();
    if (sh_last) {
        __threadfence();
        __shared__ float sm[256];
        if (tid < 256) {
            float s = 0.f;
            for (int i = tid; i < NSENT; i += 256) s += g_costs[i];
            sm[tid] = s;
        }
        __syncthreads();
        for (int ww = 128; ww; ww >>= 1) {
            if (tid < ww) sm[tid] += sm[tid + ww];
            __syncthreads();
        }
        if (tid == 0) out[0] = sm[0] / (float)NSENT;
    }
}

// ---------------------------------------------------------------------------
extern "C" void kernel_launch(void* const* d_in, const int* in_sizes, int n_in,
                              void* d_out, int out_size)
{
    const float* se  = (const float*)d_in[0];
    const float* qe  = (const float*)d_in[1];
    const float* gaf = (const float*)d_in[2];
    const int*   lab = (const int*)d_in[3];
    const float* w1  = (const float*)d_in[4];
    const float* b1  = (const float*)d_in[5];
    const float* w2  = (const float*)d_in[6];
    const float* b2  = (const float*)d_in[7];
    const float* lw  = (const float*)d_in[8];
    const float* lb  = (const float*)d_in[9];
    float* out = (float*)d_out;

    fused_kernel<<<NSENT, TPB>>>(se, qe, gaf, lab, w1, b1, w2, b2, lw, lb, out);
}

// round 16
// speedup vs baseline: 1.0032x; 1.0032x over previous
#include <cuda_runtime.h>
#include <cstdint>
#include <math.h>

// Shapes (fixed by the problem)
#define NSENT 4096
#define L     512
#define LQ    32
#define D     30
#define AF    10
#define KK    4

#define TPB 480          // 480*4 % 30 == 0 -> fixed channel phase per thread
#define GRP 16           // sentences per tail group
#define NGRP (NSENT / GRP)
#define PITCH 31         // table row pitch (avoid bank conflicts)

__device__ float        g_S[NSENT][D];
__device__ float4       g_Z[NSENT][D];
__device__ float        g_costs[NSENT];
__device__ unsigned int g_grp[NGRP];   // mod-16 epoch counters (never reset)
__device__ unsigned int g_fin;         // mod-NGRP epoch counter

// Boundary z-vector: bc[o] = sum_j dot(w1[o][j][0..3], z[j])
//   z = ( x3+2x4+3x5,  x0+x4+2x5,  2x0+x1+x5,  3x0+2x1+x2 )
__device__ __forceinline__ float4 make_z(float x0, float x1, float x2,
                                         float x3, float x4, float x5)
{
    return make_float4(x3 + 2.f * x4 + 3.f * x5,
                       x0 + x4 + 2.f * x5,
                       2.f * x0 + x1 + x5,
                       3.f * x0 + 2.f * x1 + x2);
}

// ---------------------------------------------------------------------------
// Cold tail phase: runs in 1-of-16 CTAs, overlapped with other CTAs' streaming.
// __noinline__ keeps its register pressure (and any forced spills) off the
// hot streaming path.
// ---------------------------------------------------------------------------
__device__ __noinline__ void tail_phase(
    int gbase,
    const float* __restrict__ qe,
    const float* __restrict__ gaf, const int* __restrict__ labels,
    const float* __restrict__ w1, const float* __restrict__ b1,
    const float* __restrict__ w2, const float* __restrict__ b2,
    const float* __restrict__ lw, const float* __restrict__ lb,
    float* __restrict__ out)
{
    __shared__ float4 sWv[D * PITCH];
    __shared__ float  sW2s[D * PITCH];
    __shared__ float  q0[32], q1g[32], q2g[32], qT[32], qn[3];
    __shared__ float4 qzv[32];
    __shared__ float  sS[GRP][32], sT[GRP][32];
    __shared__ float4 zbuf[GRP][32];
    __shared__ int    sh_last;

    const int tid = threadIdx.x;
    const int w = tid / 32, o = tid % 32;

    for (int i = tid; i < D * D; i += TPB) {
        int oo = i / D, jj = i % D;
        sWv[oo * PITCH + jj] = *reinterpret_cast<const float4*>(w1 + i * KK);
        const float* vv = w2 + i * KK;
        sW2s[oo * PITCH + jj] = vv[0] + vv[1] + vv[2] + vv[3];
    }
    if (w == 0) {
        float Sq = 0.f;
        if (o < D) {
            #pragma unroll
            for (int t = 0; t < LQ; t++) Sq += qe[t * D + o];
            float x0 = qe[0 * D + o],        x1 = qe[1 * D + o],        x2 = qe[2 * D + o];
            float x3 = qe[(LQ - 3) * D + o], x4 = qe[(LQ - 2) * D + o], x5 = qe[(LQ - 1) * D + o];
            qzv[o] = make_z(x0, x1, x2, x3, x4, x5);
        }
        q0[o] = (o < D) ? Sq : 0.f;
    }
    __syncthreads();   // tables + question inputs staged

    // Warp 0: question side
    if (w == 0) {
        const float invLq3 = 1.f / (float)(LQ + 3);
        float q1 = 0.f, Tv = 0.f;
        if (o < D) {
            float ds = 0.f, bc = 0.f;
            #pragma unroll
            for (int j = 0; j < D; j++) {
                float4 wv = sWv[o * PITCH + j];
                float ws = (wv.x + wv.y) + (wv.z + wv.w);
                ds += ws * q0[j];
                float4 z = qzv[j];
                bc += wv.x * z.x + wv.y * z.y + wv.z * z.z + wv.w * z.w;
            }
            q1 = b1[o] + ds * invLq3;
            Tv = (float)LQ * b1[o] + ds - 0.25f * bc;
        }
        q1g[o] = q1;
        qT[o] = Tv;
        __syncwarp();

        float q2 = 0.f;
        if (o < D) {
            float d2 = 0.f;
            #pragma unroll
            for (int j = 0; j < D; j++) d2 += sW2s[o * PITCH + j] * qT[j];
            q2 = b2[o] + d2 * invLq3;
        }
        q2g[o] = q2;
        __syncwarp();

        float n0 = q0[o] * q0[o];
        float n1 = q1 * q1;
        float n2 = q2 * q2;
        #pragma unroll
        for (int off = 16; off; off >>= 1) {
            n0 += __shfl_down_sync(0xffffffffu, n0, off);
            n1 += __shfl_down_sync(0xffffffffu, n1, off);
            n2 += __shfl_down_sync(0xffffffffu, n2, off);
        }
        if (o == 0) {
            qn[0] = rsqrtf(n0);
            qn[1] = rsqrtf(n1);
            qn[2] = rsqrtf(n2);
        }
    }

    // 16 sentences across 15 warps (warp 0 also takes sidx 15)
    float Svv[2], s1v[2], s2v[2];
    const float inv515 = 1.f / (float)(L + 3);
    #pragma unroll
    for (int rep = 0; rep < 2; rep++) {
        int sidx = w + rep * 15;
        Svv[rep] = 0.f; s1v[rep] = 0.f; s2v[rep] = 0.f;
        if (sidx < GRP) {
            int n2 = gbase + sidx;
            float Sv = 0.f;
            if (o < D) {
                Sv = g_S[n2][o];
                zbuf[sidx][o] = g_Z[n2][o];
            }
            sS[sidx][o] = Sv;
            Svv[rep] = Sv;
            __syncwarp();

            float s1 = 0.f, Tv = 0.f;
            if (o < D) {
                float ds = 0.f, bc = 0.f;
                #pragma unroll
                for (int j = 0; j < D; j++) {
                    float4 wv = sWv[o * PITCH + j];
                    float ws = (wv.x + wv.y) + (wv.z + wv.w);
                    ds += ws * sS[sidx][j];
                    float4 z = zbuf[sidx][j];
                    bc += wv.x * z.x + wv.y * z.y + wv.z * z.z + wv.w * z.w;
                }
                s1 = b1[o] + ds * inv515;
                Tv = (float)L * b1[o] + ds - 0.25f * bc;
            }
            sT[sidx][o] = Tv;
            __syncwarp();

            float s2 = 0.f;
            if (o < D) {
                float d2 = 0.f;
                #pragma unroll
                for (int j = 0; j < D; j++) d2 += sW2s[o * PITCH + j] * sT[sidx][j];
                s2 = b2[o] + d2 * inv515;
            }
            s1v[rep] = s1;
            s2v[rep] = s2;
        }
    }
    __syncthreads();   // question-side results visible

    #pragma unroll
    for (int rep = 0; rep < 2; rep++) {
        int sidx = w + rep * 15;
        if (sidx < GRP) {
            int n2 = gbase + sidx;
            float Sv = Svv[rep], s1 = s1v[rep], s2 = s2v[rep];
            float qr = 0.f, q1v = 0.f, q2v = 0.f;
            if (o < D) { qr = q0[o]; q1v = q1g[o]; q2v = q2g[o]; }

            float p0 = Sv * qr, p1 = Sv * q2v, p2 = Sv * Sv;
            float p3 = s1 * q1v, p4 = s1 * s1, p5 = s2 * q2v, p6 = s2 * s2;
            #pragma unroll
            for (int off = 16; off; off >>= 1) {
                p0 += __shfl_down_sync(0xffffffffu, p0, off);
                p1 += __shfl_down_sync(0xffffffffu, p1, off);
                p2 += __shfl_down_sync(0xffffffffu, p2, off);
                p3 += __shfl_down_sync(0xffffffffu, p3, off);
                p4 += __shfl_down_sync(0xffffffffu, p4, off);
                p5 += __shfl_down_sync(0xffffffffu, p5, off);
                p6 += __shfl_down_sync(0xffffffffu, p6, off);
            }
            if (o == 0) {
                float inv_nS = rsqrtf(p2);
                float sim1 = (n2 == 0) ? (p0 * qn[0] * inv_nS)
                                       : (p1 * qn[2] * inv_nS);
                float sim2 = p3 * rsqrtf(p4) * qn[1];
                float sim3 = p5 * rsqrtf(p6) * qn[2];

                const float* g = gaf + (size_t)n2 * AF;
                float l0 = lb[0] + lw[0] * sim1 + lw[1] * sim2 + lw[2] * sim3;
                float l1 = lb[1] + lw[13] * sim1 + lw[14] * sim2 + lw[15] * sim3;
                #pragma unroll
                for (int f = 0; f < AF; f++) {
                    float gv = g[f];
                    l0 += lw[3 + f] * gv;
                    l1 += lw[16 + f] * gv;
                }
                float mx = fmaxf(l0, l1);
                float lse = mx + logf(expf(l0 - mx) + expf(l1 - mx));
                float lp0 = l0 - lse, lp1 = l1 - lse;
                float e0 = expf(lp0), e1 = expf(lp1);
                out[1 + n2] = e1 / (e0 + e1);
                int lab = labels[n2];
                g_costs[n2] = -(lab ? lp1 : lp0);
            }
        }
    }

    // Final: last tail CTA does the deterministic cost reduction
    __syncthreads();
    if (tid == 0) {
        __threadfence();
        unsigned int old = atomicAdd(&g_fin, 1u);
        sh_last = ((old % NGRP) == NGRP - 1u) ? 1 : 0;
    }
    __syncthreads();
    if (sh_last) {
        __threadfence();
        __shared__ float sm[256];
        if (tid < 256) {
            float s = 0.f;
            for (int i = tid; i < NSENT; i += 256) s += g_costs[i];
            sm[tid] = s;
        }
        __syncthreads();
        for (int ww = 128; ww; ww >>= 1) {
            if (tid < ww) sm[tid] += sm[tid + ww];
            __syncthreads();
        }
        if (tid == 0) out[0] = sm[0] / (float)NSENT;
    }
}

// ---------------------------------------------------------------------------
// Fused kernel: hot streaming phase at occ 4 (32-reg budget), cold tail
// behind a noinline call in 1/16 CTAs.
// ---------------------------------------------------------------------------
__global__ __launch_bounds__(TPB, 4) void fused_kernel(
    const float* __restrict__ se, const float* __restrict__ qe,
    const float* __restrict__ gaf, const int* __restrict__ labels,
    const float* __restrict__ w1, const float* __restrict__ b1,
    const float* __restrict__ w2, const float* __restrict__ b2,
    const float* __restrict__ lw, const float* __restrict__ lb,
    float* __restrict__ out)
{
    __shared__ float4 part4[TPB];
    __shared__ int    sh_do;

    const int n = blockIdx.x;
    const int tid = threadIdx.x;

    // ---- Phase 1: pure streaming column-sum (R12 body, ~7.6 TB/s) ----
    {
        const float4* p = reinterpret_cast<const float4*>(se) + (size_t)n * (L * D / 4);

        float4 v0 = __ldcs(p + tid + TPB * 0);
        float4 v1 = __ldcs(p + tid + TPB * 1);
        float4 v2 = __ldcs(p + tid + TPB * 2);
        float4 v3 = __ldcs(p + tid + TPB * 3);
        float ax = (v0.x + v1.x) + (v2.x + v3.x);
        float ay = (v0.y + v1.y) + (v2.y + v3.y);
        float az = (v0.z + v1.z) + (v2.z + v3.z);
        float aw = (v0.w + v1.w) + (v2.w + v3.w);

        float4 u0 = __ldcs(p + tid + TPB * 4);
        float4 u1 = __ldcs(p + tid + TPB * 5);
        float4 u2 = __ldcs(p + tid + TPB * 6);
        float4 u3 = __ldcs(p + tid + TPB * 7);
        ax += (u0.x + u1.x) + (u2.x + u3.x);
        ay += (u0.y + u1.y) + (u2.y + u3.y);
        az += (u0.z + u1.z) + (u2.z + u3.z);
        aw += (u0.w + u1.w) + (u2.w + u3.w);

        part4[tid] = make_float4(ax, ay, az, aw);
    }
    __syncthreads();

    if (tid < D) {
        const float* part = reinterpret_cast<const float*>(part4);
        float s = 0.f;
        #pragma unroll
        for (int k = 0; k < (TPB * 4) / D; k++)
            s += part[tid + D * k];
        g_S[n][tid] = s;

        // Boundary rows: just streamed by this CTA -> cache-resident.
        const float* base = se + (size_t)n * (L * D);
        float x0 = base[0 * D + tid];
        float x1 = base[1 * D + tid];
        float x2 = base[2 * D + tid];
        float x3 = base[(L - 3) * D + tid];
        float x4 = base[(L - 2) * D + tid];
        float x5 = base[(L - 1) * D + tid];
        g_Z[n][tid] = make_z(x0, x1, x2, x3, x4, x5);
    }
    __syncthreads();

    // ---- Group-completion handoff: 15/16 CTAs exit here ----
    if (tid == 0) {
        __threadfence();
        unsigned int old = atomicAdd(&g_grp[n >> 4], 1u);
        sh_do = ((old & (GRP - 1u)) == GRP - 1u) ? 1 : 0;
    }
    __syncthreads();
    if (!sh_do) return;
    __threadfence();   // make peers' g_S/g_Z writes visible

    tail_phase((n >> 4) << 4, qe, gaf, labels, w1, b1, w2, b2, lw, lb, out);
}

// ---------------------------------------------------------------------------
extern "C" void kernel_launch(void* const* d_in, const int* in_sizes, int n_in,
                              void* d_out, int out_size)
{
    const float* se  = (const float*)d_in[0];
    const float* qe  = (const float*)d_in[1];
    const float* gaf = (const float*)d_in[2];
    const int*   lab = (const int*)d_in[3];
    const float* w1  = (const float*)d_in[4];
    const float* b1  = (const float*)d_in[5];
    const float* w2  = (const float*)d_in[6];
    const float* b2  = (const float*)d_in[7];
    const float* lw  = (const float*)d_in[8];
    const float* lb  = (const float*)d_in[9];
    float* out = (float*)d_out;

    fused_kernel<<<NSENT, TPB>>>(se, qe, gaf, lab, w1, b1, w2, b2, lw, lb, out);
}

// round 17
// speedup vs baseline: 1.1291x; 1.1255x over previous
#include <cuda_runtime.h>
#include <cstdint>
#include <math.h>

// Shapes (fixed by the problem)
#define NSENT 4096
#define L     512
#define LQ    32
#define D     30
#define AF    10
#define KK    4

#define TPB_A 480   // 480*4 % 30 == 0 -> fixed channel phase per thread
#define TPB_B 544   // 17 warps: warp 0 = question side, warps 1..16 = sentences
#define SENT_B 16
#define NBLK_B (NSENT / SENT_B)     // 256
#define PITCH 31                     // table row pitch (avoid bank conflicts)

__device__ float        g_S[NSENT][D];
__device__ float4       g_Z[NSENT][D];
__device__ float        g_costs[NSENT];
__device__ unsigned int g_fin;       // epoch counter (mod NBLK_B, never reset)

// Boundary z-vector: bc[o] = sum_j dot(w1[o][j][0..3], z[j])
//   z = ( x3+2x4+3x5,  x0+x4+2x5,  2x0+x1+x5,  3x0+2x1+x2 )
__device__ __forceinline__ float4 make_z(float x0, float x1, float x2,
                                         float x3, float x4, float x5)
{
    return make_float4(x3 + 2.f * x4 + 3.f * x5,
                       x0 + x4 + 2.f * x5,
                       2.f * x0 + x1 + x5,
                       3.f * x0 + 2.f * x1 + x2);
}

// ---------------------------------------------------------------------------
// Kernel A: pure streaming column-sum (~7.1 TB/s measured) + boundary-z fold.
// Byte-identical to the R13 version. DO NOT TOUCH.
// ---------------------------------------------------------------------------
__global__ __launch_bounds__(TPB_A, 4) void colsum_kernel(const float* __restrict__ se)
{
    __shared__ float4 part4[TPB_A];

    const int n = blockIdx.x;
    const int tid = threadIdx.x;

    const float4* p = reinterpret_cast<const float4*>(se) + (size_t)n * (L * D / 4);

    float4 v0 = __ldcs(p + tid + TPB_A * 0);
    float4 v1 = __ldcs(p + tid + TPB_A * 1);
    float4 v2 = __ldcs(p + tid + TPB_A * 2);
    float4 v3 = __ldcs(p + tid + TPB_A * 3);
    float ax = (v0.x + v1.x) + (v2.x + v3.x);
    float ay = (v0.y + v1.y) + (v2.y + v3.y);
    float az = (v0.z + v1.z) + (v2.z + v3.z);
    float aw = (v0.w + v1.w) + (v2.w + v3.w);

    float4 u0 = __ldcs(p + tid + TPB_A * 4);
    float4 u1 = __ldcs(p + tid + TPB_A * 5);
    float4 u2 = __ldcs(p + tid + TPB_A * 6);
    float4 u3 = __ldcs(p + tid + TPB_A * 7);
    ax += (u0.x + u1.x) + (u2.x + u3.x);
    ay += (u0.y + u1.y) + (u2.y + u3.y);
    az += (u0.z + u1.z) + (u2.z + u3.z);
    aw += (u0.w + u1.w) + (u2.w + u3.w);

    part4[tid] = make_float4(ax, ay, az, aw);
    __syncthreads();

    if (tid < D) {
        const float* part = reinterpret_cast<const float*>(part4);
        float s = 0.f;
        #pragma unroll
        for (int k = 0; k < (TPB_A * 4) / D; k++)
            s += part[tid + D * k];
        g_S[n][tid] = s;

        // Boundary rows: just streamed by this CTA -> cache-resident.
        const float* base = se + (size_t)n * (L * D);
        float x0 = base[0 * D + tid];
        float x1 = base[1 * D + tid];
        float x2 = base[2 * D + tid];
        float x3 = base[(L - 3) * D + tid];
        float x4 = base[(L - 2) * D + tid];
        float x5 = base[(L - 1) * D + tid];
        g_Z[n][tid] = make_z(x0, x1, x2, x3, x4, x5);
    }
}

// ---------------------------------------------------------------------------
// Kernel B (PDL secondary): prologue (tables + full question side) runs
// overlapped with colsum via programmatic launch; only the g_S/g_Z-dependent
// part waits on cudaGridDependencySynchronize().
// ---------------------------------------------------------------------------
__global__ __launch_bounds__(TPB_B) void tail_kernel(
    const float* __restrict__ qe,
    const float* __restrict__ gaf, const int* __restrict__ labels,
    const float* __restrict__ w1, const float* __restrict__ b1,
    const float* __restrict__ w2, const float* __restrict__ b2,
    const float* __restrict__ lw, const float* __restrict__ lb,
    float* __restrict__ out)
{
    __shared__ float4 sWv[D * PITCH];       // raw w1 taps (float4)
    __shared__ float  sW2s[D * PITCH];      // w2 tap-sums
    __shared__ float  q0[32], q1g[32], q2g[32], qT[32], qn[3];
    __shared__ float4 qzv[32];
    __shared__ float  sS[SENT_B][32], sT[SENT_B][32];
    __shared__ float4 zv4[SENT_B][32];
    __shared__ int    last;

    const int tid = threadIdx.x;
    const int w = tid / 32, o = tid % 32;

    // ===== PROLOGUE (independent of colsum output; overlaps primary) =====
    for (int i = tid; i < D * D; i += TPB_B) {
        int oo = i / D, jj = i % D;
        sWv[oo * PITCH + jj] = *reinterpret_cast<const float4*>(w1 + i * KK);
        const float* vv = w2 + i * KK;
        sW2s[oo * PITCH + jj] = vv[0] + vv[1] + vv[2] + vv[3];
    }
    if (w == 0) {
        float Sq = 0.f;
        if (o < D) {
            #pragma unroll
            for (int t = 0; t < LQ; t++) Sq += qe[t * D + o];
            float x0 = qe[0 * D + o],        x1 = qe[1 * D + o],        x2 = qe[2 * D + o];
            float x3 = qe[(LQ - 3) * D + o], x4 = qe[(LQ - 2) * D + o], x5 = qe[(LQ - 1) * D + o];
            qzv[o] = make_z(x0, x1, x2, x3, x4, x5);
        }
        q0[o] = (o < D) ? Sq : 0.f;
    }
    __syncthreads();   // tables + question inputs staged

    // Warp 0: full question side (still independent of colsum)
    if (w == 0) {
        const float invLq3 = 1.f / (float)(LQ + 3);
        float q1 = 0.f, Tv = 0.f;
        if (o < D) {
            float ds = 0.f, bc = 0.f;
            #pragma unroll
            for (int j = 0; j < D; j++) {
                float4 wv = sWv[o * PITCH + j];
                float ws = (wv.x + wv.y) + (wv.z + wv.w);
                ds += ws * q0[j];
                float4 z = qzv[j];
                bc += wv.x * z.x + wv.y * z.y + wv.z * z.z + wv.w * z.w;
            }
            q1 = b1[o] + ds * invLq3;
            Tv = (float)LQ * b1[o] + ds - 0.25f * bc;
        }
        q1g[o] = q1;
        qT[o] = Tv;
        __syncwarp();

        float q2 = 0.f;
        if (o < D) {
            float d2 = 0.f;
            #pragma unroll
            for (int j = 0; j < D; j++) d2 += sW2s[o * PITCH + j] * qT[j];
            q2 = b2[o] + d2 * invLq3;
        }
        q2g[o] = q2;
        __syncwarp();

        float n0 = q0[o] * q0[o];
        float n1 = q1 * q1;
        float n2 = q2 * q2;
        #pragma unroll
        for (int off = 16; off; off >>= 1) {
            n0 += __shfl_down_sync(0xffffffffu, n0, off);
            n1 += __shfl_down_sync(0xffffffffu, n1, off);
            n2 += __shfl_down_sync(0xffffffffu, n2, off);
        }
        if (o == 0) {
            qn[0] = rsqrtf(n0);
            qn[1] = rsqrtf(n1);
            qn[2] = rsqrtf(n2);
        }
    }

    // ===== WAIT for colsum grid completion (g_S/g_Z visible) =====
    cudaGridDependencySynchronize();

    // ===== DEPENDENT PART: 16 sentence tails (warps 1..16) =====
    float Sv = 0.f, s1 = 0.f, s2 = 0.f;
    if (w > 0) {
        const int sidx = w - 1;
        const int n = blockIdx.x * SENT_B + sidx;
        if (o < D) {
            Sv = g_S[n][o];
            zv4[sidx][o] = g_Z[n][o];
        }
        sS[sidx][o] = Sv;
        __syncwarp();

        const float inv515 = 1.f / (float)(L + 3);
        float Tv = 0.f;
        if (o < D) {
            float ds = 0.f, bc = 0.f;
            #pragma unroll
            for (int j = 0; j < D; j++) {
                float4 wv = sWv[o * PITCH + j];
                float wsum = (wv.x + wv.y) + (wv.z + wv.w);
                ds += wsum * sS[sidx][j];
                float4 z = zv4[sidx][j];
                bc += wv.x * z.x + wv.y * z.y + wv.z * z.z + wv.w * z.w;
            }
            s1 = b1[o] + ds * inv515;
            Tv = (float)L * b1[o] + ds - 0.25f * bc;
        }
        sT[sidx][o] = Tv;
        __syncwarp();

        if (o < D) {
            float d2 = 0.f;
            #pragma unroll
            for (int j = 0; j < D; j++) d2 += sW2s[o * PITCH + j] * sT[sidx][j];
            s2 = b2[o] + d2 * inv515;
        }
    }

    __syncthreads();   // question-side results (q0/q1g/q2g/qn) visible

    if (w > 0) {
        const int n = blockIdx.x * SENT_B + (w - 1);
        float qr = 0.f, q1v = 0.f, q2v = 0.f;
        if (o < D) { qr = q0[o]; q1v = q1g[o]; q2v = q2g[o]; }

        float p0 = Sv * qr, p1 = Sv * q2v, p2 = Sv * Sv;
        float p3 = s1 * q1v, p4 = s1 * s1, p5 = s2 * q2v, p6 = s2 * s2;
        #pragma unroll
        for (int off = 16; off; off >>= 1) {
            p0 += __shfl_down_sync(0xffffffffu, p0, off);
            p1 += __shfl_down_sync(0xffffffffu, p1, off);
            p2 += __shfl_down_sync(0xffffffffu, p2, off);
            p3 += __shfl_down_sync(0xffffffffu, p3, off);
            p4 += __shfl_down_sync(0xffffffffu, p4, off);
            p5 += __shfl_down_sync(0xffffffffu, p5, off);
            p6 += __shfl_down_sync(0xffffffffu, p6, off);
        }
        if (o == 0) {
            float inv_nS = rsqrtf(p2);
            float sim1 = (n == 0) ? (p0 * qn[0] * inv_nS)
                                  : (p1 * qn[2] * inv_nS);
            float sim2 = p3 * rsqrtf(p4) * qn[1];
            float sim3 = p5 * rsqrtf(p6) * qn[2];

            const float* g = gaf + (size_t)n * AF;
            float l0 = lb[0] + lw[0] * sim1 + lw[1] * sim2 + lw[2] * sim3;
            float l1 = lb[1] + lw[13] * sim1 + lw[14] * sim2 + lw[15] * sim3;
            #pragma unroll
            for (int f = 0; f < AF; f++) {
                float gv = g[f];
                l0 += lw[3 + f] * gv;
                l1 += lw[16 + f] * gv;
            }
            float mx = fmaxf(l0, l1);
            float lse = mx + logf(expf(l0 - mx) + expf(l1 - mx));
            float lp0 = l0 - lse, lp1 = l1 - lse;
            float e0 = expf(lp0), e1 = expf(lp1);
            out[1 + n] = e1 / (e0 + e1);
            int lab = labels[n];
            g_costs[n] = -(lab ? lp1 : lp0);
        }
    }

    // Last block: deterministic cost reduction (epoch counter, no reset)
    __syncthreads();
    if (tid == 0) {
        __threadfence();
        unsigned int old = atomicAdd(&g_fin, 1u);
        last = ((old % NBLK_B) == NBLK_B - 1u) ? 1 : 0;
    }
    __syncthreads();
    if (last) {
        __threadfence();
        __shared__ float sm[256];
        if (tid < 256) {
            float s = 0.f;
            for (int i = tid; i < NSENT; i += 256) s += g_costs[i];
            sm[tid] = s;
        }
        __syncthreads();
        for (int ww = 128; ww; ww >>= 1) {
            if (tid < ww) sm[tid] += sm[tid + ww];
            __syncthreads();
        }
        if (tid == 0) out[0] = sm[0] / (float)NSENT;
    }
}

// ---------------------------------------------------------------------------
extern "C" void kernel_launch(void* const* d_in, const int* in_sizes, int n_in,
                              void* d_out, int out_size)
{
    const float* se  = (const float*)d_in[0];
    const float* qe  = (const float*)d_in[1];
    const float* gaf = (const float*)d_in[2];
    const int*   lab = (const int*)d_in[3];
    const float* w1  = (const float*)d_in[4];
    const float* b1  = (const float*)d_in[5];
    const float* w2  = (const float*)d_in[6];
    const float* b2  = (const float*)d_in[7];
    const float* lw  = (const float*)d_in[8];
    const float* lb  = (const float*)d_in[9];
    float* out = (float*)d_out;

    // Primary: streaming column-sum
    colsum_kernel<<<NSENT, TPB_A>>>(se);

    // Secondary: PDL launch — prologue overlaps colsum, dependent part gated
    // by cudaGridDependencySynchronize() inside the kernel.
    cudaLaunchConfig_t cfg = {};
    cfg.gridDim  = dim3(NBLK_B, 1, 1);
    cfg.blockDim = dim3(TPB_B, 1, 1);
    cfg.dynamicSmemBytes = 0;
    cfg.stream = 0;
    cudaLaunchAttribute attrs[1];
    attrs[0].id = cudaLaunchAttributeProgrammaticStreamSerialization;
    attrs[0].val.programmaticStreamSerializationAllowed = 1;
    cfg.attrs = attrs;
    cfg.numAttrs = 1;
    cudaLaunchKernelEx(&cfg, tail_kernel,
                       qe, gaf, lab, w1, b1, w2, b2, lw, lb, out);
}